// round 2
// baseline (speedup 1.0000x reference)
#include <cuda_runtime.h>
#include <math.h>

// ---------------------------------------------------------------------------
// BERT-base forward, fp32 baseline.
// B=8 S=512 D=768 H=12 DK=64 F=3072 L=12
// ---------------------------------------------------------------------------
#define BB 8
#define SS 512
#define DD 768
#define HH 12
#define DKK 64
#define FF 3072
#define LL 12
#define MTOK (BB*SS)          // 4096 tokens
#define NHB (BB*HH)           // 96 (batch*heads)
#define SCALE 0.125f          // 1/sqrt(64)

// ------------------------------- scratch -----------------------------------
__device__ float g_x[MTOK*DD];
__device__ float g_q[MTOK*DD];
__device__ float g_k[MTOK*DD];
__device__ float g_v[MTOK*DD];
__device__ float g_c[MTOK*DD];
__device__ float g_t[MTOK*DD];
__device__ float g_a[MTOK*DD];
__device__ float g_h[MTOK*FF];
__device__ float g_s[(long)NHB*SS*SS];

// --------------------------- block reductions -------------------------------
__device__ __forceinline__ float block_sum256(float v, float* sh) {
    int lane = threadIdx.x & 31, w = threadIdx.x >> 5;
    #pragma unroll
    for (int o = 16; o > 0; o >>= 1) v += __shfl_xor_sync(0xffffffffu, v, o);
    if (lane == 0) sh[w] = v;
    __syncthreads();
    float r = 0.f;
    #pragma unroll
    for (int i = 0; i < 8; i++) r += sh[i];
    __syncthreads();
    return r;
}

__device__ __forceinline__ float block_max256(float v, float* sh) {
    int lane = threadIdx.x & 31, w = threadIdx.x >> 5;
    #pragma unroll
    for (int o = 16; o > 0; o >>= 1) v = fmaxf(v, __shfl_xor_sync(0xffffffffu, v, o));
    if (lane == 0) sh[w] = v;
    __syncthreads();
    float r = -1e30f;
    #pragma unroll
    for (int i = 0; i < 8; i++) r = fmaxf(r, sh[i]);
    __syncthreads();
    return r;
}

// -------------------------- embedding + LN ----------------------------------
// one block per token, 256 threads, 3 elems/thread over D=768
__global__ void embed_ln_kernel(const int* __restrict__ ids,
                                const int* __restrict__ tt,
                                const float* __restrict__ we,
                                const float* __restrict__ pe,
                                const float* __restrict__ te,
                                const float* __restrict__ gamma,
                                const float* __restrict__ beta,
                                float* __restrict__ out) {
    __shared__ float sh[8];
    int m = blockIdx.x;
    int s = m & (SS - 1);
    int id = ids[m];
    int ty = tt[m];
    int t = threadIdx.x;
    float v[3];
    #pragma unroll
    for (int i = 0; i < 3; i++) {
        int d = t + i * 256;
        v[i] = we[(long)id * DD + d] + te[(long)ty * DD + d] + pe[(long)s * DD + d];
    }
    float sum = block_sum256(v[0] + v[1] + v[2], sh);
    float mu = sum * (1.f / DD);
    float qs = 0.f;
    #pragma unroll
    for (int i = 0; i < 3; i++) { float d0 = v[i] - mu; qs += d0 * d0; }
    qs = block_sum256(qs, sh);
    float rstd = rsqrtf(qs * (1.f / DD) + 1e-12f);
    #pragma unroll
    for (int i = 0; i < 3; i++) {
        int d = t + i * 256;
        out[(long)m * DD + d] = (v[i] - mu) * rstd * gamma[d] + beta[d];
    }
}

// ------------------------------ LN (768) -------------------------------------
// out = LN(in + bias + resid) ; bias/resid nullable
__global__ void ln768_kernel(const float* __restrict__ in,
                             const float* __restrict__ resid,
                             const float* __restrict__ bias,
                             const float* __restrict__ gamma,
                             const float* __restrict__ beta,
                             float* __restrict__ out, float eps) {
    __shared__ float sh[8];
    long m = blockIdx.x;
    int t = threadIdx.x;
    float v[3];
    #pragma unroll
    for (int i = 0; i < 3; i++) {
        int d = t + i * 256;
        float x = in[m * DD + d];
        if (bias) x += bias[d];
        if (resid) x += resid[m * DD + d];
        v[i] = x;
    }
    float sum = block_sum256(v[0] + v[1] + v[2], sh);
    float mu = sum * (1.f / DD);
    float qs = 0.f;
    #pragma unroll
    for (int i = 0; i < 3; i++) { float d0 = v[i] - mu; qs += d0 * d0; }
    qs = block_sum256(qs, sh);
    float rstd = rsqrtf(qs * (1.f / DD) + eps);
    #pragma unroll
    for (int i = 0; i < 3; i++) {
        int d = t + i * 256;
        out[m * DD + d] = (v[i] - mu) * rstd * gamma[d] + beta[d];
    }
}

// ------------------------------ GEMM NT --------------------------------------
// C[m,n] = alpha * sum_k A[m,k]*B[n,k] (+ bias[n])
// A: M x K row-major (+ z*sA), B: N x K row-major (+ z*sB), C offset z*sC.
// mode 0: C[m*N+n].  mode 1: head-permute -> out[((b*H+h)*S+s)*DK+dk]
// Tiles: 64x64x32, 256 threads, 4x4 microtile.
__global__ void gemm_nt_kernel(const float* __restrict__ A, long sA,
                               const float* __restrict__ Bm, long sB,
                               const float* __restrict__ bias,
                               float* __restrict__ C, long sC,
                               int M, int N, int K, float alpha, int mode) {
    __shared__ float As[64][33];
    __shared__ float Bs[64][33];
    int z = blockIdx.z;
    A += (long)z * sA;
    Bm += (long)z * sB;
    C += (long)z * sC;
    int tid = threadIdx.x;
    int tx = tid & 15, ty = tid >> 4;
    int m0 = blockIdx.y * 64;
    int n0 = blockIdx.x * 64;
    float acc[4][4] = {};
    for (int k0 = 0; k0 < K; k0 += 32) {
        #pragma unroll
        for (int i = 0; i < 8; i++) {
            int li = tid + i * 256;
            int r = li >> 5, c = li & 31;
            As[r][c] = A[(long)(m0 + r) * K + k0 + c];
            Bs[r][c] = Bm[(long)(n0 + r) * K + k0 + c];
        }
        __syncthreads();
        #pragma unroll
        for (int kk = 0; kk < 32; kk++) {
            float ra[4], rb[4];
            #pragma unroll
            for (int i = 0; i < 4; i++) ra[i] = As[ty * 4 + i][kk];
            #pragma unroll
            for (int j = 0; j < 4; j++) rb[j] = Bs[tx * 4 + j][kk];
            #pragma unroll
            for (int i = 0; i < 4; i++)
                #pragma unroll
                for (int j = 0; j < 4; j++)
                    acc[i][j] += ra[i] * rb[j];
        }
        __syncthreads();
    }
    #pragma unroll
    for (int i = 0; i < 4; i++) {
        int m = m0 + ty * 4 + i;
        #pragma unroll
        for (int j = 0; j < 4; j++) {
            int n = n0 + tx * 4 + j;
            float val = acc[i][j] * alpha;
            if (bias) val += bias[n];
            if (mode == 0) {
                C[(long)m * N + n] = val;
            } else {
                // permute [token, e] -> [b, h, s, dk]
                int b = m >> 9, s = m & (SS - 1);
                int h = n >> 6, dk = n & (DKK - 1);
                C[(((long)(b * HH + h) * SS) + s) * DKK + dk] = val;
            }
        }
    }
}

// ------------------------------ softmax --------------------------------------
// one block per score row; 256 threads, 2 elems each over S=512
__global__ void softmax_kernel(float* __restrict__ scores,
                               const float* __restrict__ amask) {
    __shared__ float sh[8];
    int z = blockIdx.y;            // b*H + h
    int qr = blockIdx.x;           // query row
    int b = z / HH;
    float* row = scores + ((long)z * SS + qr) * SS;
    int t = threadIdx.x;
    float v[2];
    #pragma unroll
    for (int i = 0; i < 2; i++) {
        int k = t + i * 256;
        float s = row[k];
        if (amask[b * SS + k] == 0.f) s = -1e9f;
        v[i] = s;
    }
    float mx = block_max256(fmaxf(v[0], v[1]), sh);
    float e0 = __expf(v[0] - mx);
    float e1 = __expf(v[1] - mx);
    float sum = block_sum256(e0 + e1, sh);
    float inv = 1.f / sum;
    row[t] = e0 * inv;
    row[t + 256] = e1 * inv;
}

// ------------------------------ P @ V ----------------------------------------
// per z=b*H+h:  ctx[b, q, h*64+dk] = sum_k P[z,q,k] * V[z,k,dk]
// BM=64, BN=64(=DK), BK=32.
__global__ void gemm_pv_kernel(const float* __restrict__ P,
                               const float* __restrict__ V,
                               float* __restrict__ ctx) {
    __shared__ float As[64][33];   // P tile [m][k]
    __shared__ float Bs[32][65];   // V tile [k][n]
    int z = blockIdx.z;
    int b = z / HH, h = z % HH;
    const float* Pz = P + (long)z * SS * SS;
    const float* Vz = V + (long)z * SS * DKK;
    int tid = threadIdx.x;
    int tx = tid & 15, ty = tid >> 4;
    int m0 = blockIdx.y * 64;
    float acc[4][4] = {};
    for (int k0 = 0; k0 < SS; k0 += 32) {
        #pragma unroll
        for (int i = 0; i < 8; i++) {
            int li = tid + i * 256;
            int r = li >> 5, c = li & 31;
            As[r][c] = Pz[(long)(m0 + r) * SS + k0 + c];
            int r2 = li >> 6, c2 = li & 63;
            Bs[r2][c2] = Vz[(long)(k0 + r2) * DKK + c2];
        }
        __syncthreads();
        #pragma unroll
        for (int kk = 0; kk < 32; kk++) {
            float ra[4], rb[4];
            #pragma unroll
            for (int i = 0; i < 4; i++) ra[i] = As[ty * 4 + i][kk];
            #pragma unroll
            for (int j = 0; j < 4; j++) rb[j] = Bs[kk][tx * 4 + j];
            #pragma unroll
            for (int i = 0; i < 4; i++)
                #pragma unroll
                for (int j = 0; j < 4; j++)
                    acc[i][j] += ra[i] * rb[j];
        }
        __syncthreads();
    }
    #pragma unroll
    for (int i = 0; i < 4; i++) {
        int q = m0 + ty * 4 + i;
        #pragma unroll
        for (int j = 0; j < 4; j++) {
            int dk = tx * 4 + j;
            ctx[((long)(b * SS + q) * DD) + h * DKK + dk] = acc[i][j];
        }
    }
}

// ------------------------------- launch --------------------------------------
extern "C" void kernel_launch(void* const* d_in, const int* in_sizes, int n_in,
                              void* d_out, int out_size) {
    const int*   input_ids = (const int*)  d_in[0];
    const int*   type_ids  = (const int*)  d_in[1];
    const float* amask     = (const float*)d_in[2];
    const float* word_emb  = (const float*)d_in[3];
    const float* pos_emb   = (const float*)d_in[4];
    const float* type_emb  = (const float*)d_in[5];
    const float* emb_g     = (const float*)d_in[6];
    const float* emb_b     = (const float*)d_in[7];
    const float* Wq = (const float*)d_in[8];
    const float* bq = (const float*)d_in[9];
    const float* Wk = (const float*)d_in[10];
    const float* bk = (const float*)d_in[11];
    const float* Wv = (const float*)d_in[12];
    const float* bv = (const float*)d_in[13];
    const float* Wo = (const float*)d_in[14];
    const float* bo = (const float*)d_in[15];
    const float* ag = (const float*)d_in[16];
    const float* ab = (const float*)d_in[17];
    const float* W1 = (const float*)d_in[18];
    const float* b1 = (const float*)d_in[19];
    const float* W2 = (const float*)d_in[20];
    const float* b2 = (const float*)d_in[21];
    const float* fg = (const float*)d_in[22];
    const float* fb = (const float*)d_in[23];

    float *x, *q, *k, *v, *c, *t, *a, *h, *s;
    cudaGetSymbolAddress((void**)&x, g_x);
    cudaGetSymbolAddress((void**)&q, g_q);
    cudaGetSymbolAddress((void**)&k, g_k);
    cudaGetSymbolAddress((void**)&v, g_v);
    cudaGetSymbolAddress((void**)&c, g_c);
    cudaGetSymbolAddress((void**)&t, g_t);
    cudaGetSymbolAddress((void**)&a, g_a);
    cudaGetSymbolAddress((void**)&h, g_h);
    cudaGetSymbolAddress((void**)&s, g_s);

    embed_ln_kernel<<<MTOK, 256>>>(input_ids, type_ids, word_emb, pos_emb,
                                   type_emb, emb_g, emb_b, x);

    for (int l = 0; l < LL; l++) {
        const float* wq = Wq + (long)l * DD * DD;
        const float* wk = Wk + (long)l * DD * DD;
        const float* wv = Wv + (long)l * DD * DD;
        const float* wo = Wo + (long)l * DD * DD;
        const float* w1 = W1 + (long)l * FF * DD;
        const float* w2 = W2 + (long)l * DD * FF;

        dim3 gProj(DD / 64, MTOK / 64, 1);
        // Q,K,V projections, written head-permuted [b,h,s,dk]
        gemm_nt_kernel<<<gProj, 256>>>(x, 0, wq, 0, bq + l * DD, q, 0,
                                       MTOK, DD, DD, 1.f, 1);
        gemm_nt_kernel<<<gProj, 256>>>(x, 0, wk, 0, bk + l * DD, k, 0,
                                       MTOK, DD, DD, 1.f, 1);
        gemm_nt_kernel<<<gProj, 256>>>(x, 0, wv, 0, bv + l * DD, v, 0,
                                       MTOK, DD, DD, 1.f, 1);
        // scores = scale * Q K^T  (batched over 96 heads)
        dim3 gSc(SS / 64, SS / 64, NHB);
        gemm_nt_kernel<<<gSc, 256>>>(q, (long)SS * DKK, k, (long)SS * DKK,
                                     nullptr, s, (long)SS * SS,
                                     SS, SS, DKK, SCALE, 0);
        dim3 gSm(SS, NHB, 1);
        softmax_kernel<<<gSm, 256>>>(s, amask);
        // ctx = P V  (writes back to [b,s,e] layout)
        dim3 gPv(1, SS / 64, NHB);
        gemm_pv_kernel<<<gPv, 256>>>(s, v, c);
        // O projection (bias folded into LN)
        gemm_nt_kernel<<<gProj, 256>>>(c, 0, wo, 0, nullptr, t, 0,
                                       MTOK, DD, DD, 1.f, 0);
        ln768_kernel<<<MTOK, 256>>>(t, x, bo + l * DD, ag + l * DD, ab + l * DD,
                                    a, 1e-5f);
        // FFN
        dim3 gF1(FF / 64, MTOK / 64, 1);
        gemm_nt_kernel<<<gF1, 256>>>(a, 0, w1, 0, b1 + l * FF, h, 0,
                                     MTOK, FF, DD, 1.f, 0);
        gemm_nt_kernel<<<gProj, 256>>>(h, 0, w2, 0, nullptr, t, 0,
                                       MTOK, DD, FF, 1.f, 0);
        ln768_kernel<<<MTOK, 256>>>(t, nullptr, b2 + l * DD, fg + l * DD,
                                    fb + l * DD, x, 1e-5f);
    }

    cudaMemcpyAsync(d_out, x, (size_t)MTOK * DD * sizeof(float),
                    cudaMemcpyDeviceToDevice);
}